// round 10
// baseline (speedup 1.0000x reference)
#include <cuda_runtime.h>

// QNN via Heisenberg-picture Pauli propagation. Grid-stride, 2 samples/thread
// sequential (register-reusing), single wave: 1024 blocks x 256 thr @ 8 blk/SM.
// z_q = 30 sparse monomials in C_j=cos(x_j+w0_j), S_j=sin(x_j+w0_j);
// coefficients (from w1,w2) computed once per block. Head in log2 domain,
// softmax via raw ex2.approx + rcp.approx (1 MUFU each).
// Inputs: x [B,4] f32, qw [3,4] f32, W [6,4] f32, b [6] f32. Out: [B,6] f32.

#define LOG2E 1.4426950408889634f

__device__ __forceinline__ float ex2_approx(float v) {
    float r; asm("ex2.approx.ftz.f32 %0, %1;" : "=f"(r) : "f"(v)); return r;
}
__device__ __forceinline__ float rcp_approx(float v) {
    float r; asm("rcp.approx.ftz.f32 %0, %1;" : "=f"(r) : "f"(v)); return r;
}

__global__ __launch_bounds__(256, 8) void qnn_kernel(
    const float4* __restrict__ x,
    const float*  __restrict__ qw,
    const float*  __restrict__ W,
    const float*  __restrict__ bias,
    float2*       __restrict__ out,
    int B)
{
    __shared__ float w0s[4];
    __shared__ float trig[16];
    __shared__ float A0[6], A1[5], A2[6], A3[13];
    __shared__ __align__(16) float4 W4[6];
    __shared__ float bs[6];

    int t = threadIdx.x;

    if (t < 4) {
        w0s[t] = qw[t];
        float s, c;
        __sincosf(qw[4 + t], &s, &c); trig[t] = c;     trig[4 + t]  = s;
        __sincosf(qw[8 + t], &s, &c); trig[8 + t] = c; trig[12 + t] = s;
    }
    if (t < 24) ((float*)W4)[t] = W[t] * LOG2E;
    if (t < 6)  bs[t] = bias[t] * LOG2E;
    __syncthreads();

    if (t == 0) {
        float c0 = trig[0], c1 = trig[1], c2 = trig[2], c3 = trig[3];
        float s0 = trig[4], s1 = trig[5], s2 = trig[6], s3 = trig[7];
        float u0 = trig[8], u1 = trig[9], u2 = trig[10], u3 = trig[11];
        float v0 = trig[12], v1 = trig[13], v2 = trig[14], v3 = trig[15];

        A0[0] =  u0 * c1 * c2 * c3;
        A0[1] = -u0 * c1 * c2 * s3;
        A0[2] = -u0 * s1 * c2 * c3;
        A0[3] = -u0 * s1 * s2 * s3;
        A0[4] = -v0 * s0 * s1;
        A0[5] = -v0 * c0 * c1;

        A1[0] =  u1 * c0 * c1;
        A1[1] =  u1 * s0 * s1;
        A1[2] = -v1 * s1 * s2;
        A1[3] = -v1 * s1 * c2;
        A1[4] = -v1 * c1 * c2;

        A2[0] =  u2 * c0 * c1 * c2;
        A2[1] = -u2 * c0 * s1 * c2;
        A2[2] = -u2 * s0 * c1 * c2;
        A2[3] = -u2 * s0 * s1 * s2;
        A2[4] = -v2 * s2 * s3;
        A2[5] = -v2 * c2 * c3;

        A3[0]  =  u3 * c0 * c1 * c2 * c3;
        A3[1]  = -u3 * c0 * c1 * s2 * c3;
        A3[2]  =  u3 * c0 * s1 * s2 * c3;
        A3[3]  = -u3 * c0 * s1 * s2 * s3;
        A3[4]  =  u3 * s0 * c1 * c2 * s3;
        A3[5]  = -u3 * s0 * c1 * s2 * s3;
        A3[6]  =  u3 * s0 * s1 * c2 * c3;
        A3[7]  =  u3 * s0 * s1 * s2 * s3;
        A3[8]  = -v3 * c0 * c1 * c3;
        A3[9]  = -v3 * c0 * s1 * c3;
        A3[10] = -v3 * c0 * s1 * s3;
        A3[11] = -v3 * s0 * c1 * s3;
        A3[12] = -v3 * s0 * s1 * s3;
    }
    __syncthreads();

    const int stride = gridDim.x * 256;

    for (int i = blockIdx.x * 256 + t; i < B; i += stride) {
        float4 xv = x[i];

        float C0, S0, C1, S1, C2, S2, C3, S3;
        __sincosf(xv.x + w0s[0], &S0, &C0);
        __sincosf(xv.y + w0s[1], &S1, &C1);
        __sincosf(xv.z + w0s[2], &S2, &C2);
        __sincosf(xv.w + w0s[3], &S3, &C3);

        float pc01 = C0 * C1, pc23 = C2 * C3, pc02 = C0 * C2, pc13 = C1 * C3;
        float ps01 = S0 * S1, ps23 = S2 * S3, ps02 = S0 * S2, ps13 = S1 * S3;
        float ps12 = S1 * S2, ps03 = S0 * S3, pcs23 = C2 * S3;
        float c0c2c3 = C0 * pc23;
        float c0s1s2 = C0 * ps12;

        float z0 = A0[0] * (pc01 * C3);
        z0 = fmaf(A0[1], ps01 * pcs23, z0);
        z0 = fmaf(A0[2], ps12 * C3, z0);
        z0 = fmaf(A0[3], S0, z0);
        z0 = fmaf(A0[4], c0c2c3, z0);
        z0 = fmaf(A0[5], ps02, z0);

        float z1 = A1[0] * c0c2c3;
        z1 = fmaf(A1[1], ps02, z1);
        z1 = fmaf(A1[2], C2, z1);
        z1 = fmaf(A1[3], pc01 * ps23, z1);
        z1 = fmaf(A1[4], ps13, z1);

        float z2 = A2[0] * pc13;
        z2 = fmaf(A2[1], c0s1s2 * C3, z2);
        z2 = fmaf(A2[2], ps01 * C2, z2);
        z2 = fmaf(A2[3], ps03, z2);
        z2 = fmaf(A2[4], C3, z2);
        z2 = fmaf(A2[5], ps01 * S2, z2);

        float z3 = A3[0] * pc02;
        z3 = fmaf(A3[1],  C1 * ps23, z3);
        z3 = fmaf(A3[2],  C0 * ps13, z3);
        z3 = fmaf(A3[3],  S0 * (C1 * pc23), z3);
        z3 = fmaf(A3[4],  pcs23, z3);
        z3 = fmaf(A3[5],  pc01 * S2, z3);
        z3 = fmaf(A3[6],  ps02 * C3, z3);
        z3 = fmaf(A3[7],  S1, z3);
        z3 = fmaf(A3[8],  S1 * ps23, z3);
        z3 = fmaf(A3[9],  pc01 * S3, z3);
        z3 = fmaf(A3[10], ps01 * pc23, z3);
        z3 = fmaf(A3[11], c0s1s2, z3);
        z3 = fmaf(A3[12], C1, z3);

        // head in log2 domain + softmax via ex2.approx
        float eo[6];
        #pragma unroll
        for (int k = 0; k < 6; k++) {
            float4 w = W4[k];
            float acc = bs[k];
            acc = fmaf(w.x, z0, acc);
            acc = fmaf(w.y, z1, acc);
            acc = fmaf(w.z, z2, acc);
            acc = fmaf(w.w, z3, acc);
            eo[k] = ex2_approx(acc);
        }
        float ssum = ((eo[0] + eo[1]) + (eo[2] + eo[3])) + (eo[4] + eo[5]);
        float inv = rcp_approx(ssum);

        out[i * 3 + 0] = make_float2(eo[0] * inv, eo[1] * inv);
        out[i * 3 + 1] = make_float2(eo[2] * inv, eo[3] * inv);
        out[i * 3 + 2] = make_float2(eo[4] * inv, eo[5] * inv);
    }
}

extern "C" void kernel_launch(void* const* d_in, const int* in_sizes, int n_in,
                              void* d_out, int out_size) {
    const float4* x  = (const float4*)d_in[0];
    const float*  qw = (const float*)d_in[1];
    const float*  W  = (const float*)d_in[2];
    const float*  b  = (const float*)d_in[3];
    float2* out = (float2*)d_out;
    int B = in_sizes[0] / 4;
    int threads = 256;
    // single co-resident wave: 1024 blocks < 152 SM x 8 blocks; 2 iters/thread
    int blocks = 1024;
    int per_grid = blocks * threads;
    if (B < per_grid) blocks = (B + threads - 1) / threads;
    qnn_kernel<<<blocks, threads>>>(x, qw, W, b, out, B);
}

// round 11
// speedup vs baseline: 2.1065x; 2.1065x over previous
#include <cuda_runtime.h>

// QNN via Heisenberg-picture Pauli propagation. One sample per thread.
// z_q = 30 sparse monomials in C_j=cos(x_j+w0_j), S_j=sin(x_j+w0_j);
// coefficients (from w1,w2) computed once per block. Head in log2 domain,
// softmax via raw ex2.approx / rcp.approx. Outputs staged through shared
// memory for fully coalesced STG.128.
// Inputs: x [B,4] f32, qw [3,4] f32, W [6,4] f32, b [6] f32. Out: [B,6] f32.

#define LOG2E 1.4426950408889634f

__device__ __forceinline__ float ex2_approx(float v) {
    float r; asm("ex2.approx.ftz.f32 %0, %1;" : "=f"(r) : "f"(v)); return r;
}
__device__ __forceinline__ float rcp_approx(float v) {
    float r; asm("rcp.approx.ftz.f32 %0, %1;" : "=f"(r) : "f"(v)); return r;
}

__global__ __launch_bounds__(256, 8) void qnn_kernel(
    const float4* __restrict__ x,
    const float*  __restrict__ qw,
    const float*  __restrict__ W,
    const float*  __restrict__ bias,
    float*        __restrict__ out,
    int B)
{
    __shared__ float w0s[4];
    __shared__ float trig[16];
    __shared__ float A0[6], A1[5], A2[6], A3[13];
    __shared__ __align__(16) float4 W4[6];
    __shared__ float bs[6];
    __shared__ __align__(16) float obuf[256 * 6];   // staged outputs (6 KB)

    int t = threadIdx.x;
    int i = blockIdx.x * 256 + t;

    // hoist input load: DRAM latency overlaps the setup barriers
    float4 xv = (i < B) ? x[i] : make_float4(0.f, 0.f, 0.f, 0.f);

    if (t < 4) {
        w0s[t] = qw[t];
        float s, c;
        __sincosf(qw[4 + t], &s, &c); trig[t] = c;     trig[4 + t]  = s;
        __sincosf(qw[8 + t], &s, &c); trig[8 + t] = c; trig[12 + t] = s;
    }
    if (t < 24) ((float*)W4)[t] = W[t] * LOG2E;
    if (t < 6)  bs[t] = bias[t] * LOG2E;
    __syncthreads();

    if (t == 0) {
        float c0 = trig[0], c1 = trig[1], c2 = trig[2], c3 = trig[3];
        float s0 = trig[4], s1 = trig[5], s2 = trig[6], s3 = trig[7];
        float u0 = trig[8], u1 = trig[9], u2 = trig[10], u3 = trig[11];
        float v0 = trig[12], v1 = trig[13], v2 = trig[14], v3 = trig[15];

        A0[0] =  u0 * c1 * c2 * c3;
        A0[1] = -u0 * c1 * c2 * s3;
        A0[2] = -u0 * s1 * c2 * c3;
        A0[3] = -u0 * s1 * s2 * s3;
        A0[4] = -v0 * s0 * s1;
        A0[5] = -v0 * c0 * c1;

        A1[0] =  u1 * c0 * c1;
        A1[1] =  u1 * s0 * s1;
        A1[2] = -v1 * s1 * s2;
        A1[3] = -v1 * s1 * c2;
        A1[4] = -v1 * c1 * c2;

        A2[0] =  u2 * c0 * c1 * c2;
        A2[1] = -u2 * c0 * s1 * c2;
        A2[2] = -u2 * s0 * c1 * c2;
        A2[3] = -u2 * s0 * s1 * s2;
        A2[4] = -v2 * s2 * s3;
        A2[5] = -v2 * c2 * c3;

        A3[0]  =  u3 * c0 * c1 * c2 * c3;
        A3[1]  = -u3 * c0 * c1 * s2 * c3;
        A3[2]  =  u3 * c0 * s1 * s2 * c3;
        A3[3]  = -u3 * c0 * s1 * s2 * s3;
        A3[4]  =  u3 * s0 * c1 * c2 * s3;
        A3[5]  = -u3 * s0 * c1 * s2 * s3;
        A3[6]  =  u3 * s0 * s1 * c2 * c3;
        A3[7]  =  u3 * s0 * s1 * s2 * s3;
        A3[8]  = -v3 * c0 * c1 * c3;
        A3[9]  = -v3 * c0 * s1 * c3;
        A3[10] = -v3 * c0 * s1 * s3;
        A3[11] = -v3 * s0 * c1 * s3;
        A3[12] = -v3 * s0 * s1 * s3;
    }
    __syncthreads();

    float C0, S0, C1, S1, C2, S2, C3, S3;
    __sincosf(xv.x + w0s[0], &S0, &C0);
    __sincosf(xv.y + w0s[1], &S1, &C1);
    __sincosf(xv.z + w0s[2], &S2, &C2);
    __sincosf(xv.w + w0s[3], &S3, &C3);

    float pc01 = C0 * C1, pc23 = C2 * C3, pc02 = C0 * C2, pc13 = C1 * C3;
    float ps01 = S0 * S1, ps23 = S2 * S3, ps02 = S0 * S2, ps13 = S1 * S3;
    float ps12 = S1 * S2, ps03 = S0 * S3, pcs23 = C2 * S3;
    float c0c2c3 = C0 * pc23;
    float c0s1s2 = C0 * ps12;

    float z0 = A0[0] * (pc01 * C3);
    z0 = fmaf(A0[1], ps01 * pcs23, z0);
    z0 = fmaf(A0[2], ps12 * C3, z0);
    z0 = fmaf(A0[3], S0, z0);
    z0 = fmaf(A0[4], c0c2c3, z0);
    z0 = fmaf(A0[5], ps02, z0);

    float z1 = A1[0] * c0c2c3;
    z1 = fmaf(A1[1], ps02, z1);
    z1 = fmaf(A1[2], C2, z1);
    z1 = fmaf(A1[3], pc01 * ps23, z1);
    z1 = fmaf(A1[4], ps13, z1);

    float z2 = A2[0] * pc13;
    z2 = fmaf(A2[1], c0s1s2 * C3, z2);
    z2 = fmaf(A2[2], ps01 * C2, z2);
    z2 = fmaf(A2[3], ps03, z2);
    z2 = fmaf(A2[4], C3, z2);
    z2 = fmaf(A2[5], ps01 * S2, z2);

    float z3 = A3[0] * pc02;
    z3 = fmaf(A3[1],  C1 * ps23, z3);
    z3 = fmaf(A3[2],  C0 * ps13, z3);
    z3 = fmaf(A3[3],  S0 * (C1 * pc23), z3);
    z3 = fmaf(A3[4],  pcs23, z3);
    z3 = fmaf(A3[5],  pc01 * S2, z3);
    z3 = fmaf(A3[6],  ps02 * C3, z3);
    z3 = fmaf(A3[7],  S1, z3);
    z3 = fmaf(A3[8],  S1 * ps23, z3);
    z3 = fmaf(A3[9],  pc01 * S3, z3);
    z3 = fmaf(A3[10], ps01 * pc23, z3);
    z3 = fmaf(A3[11], c0s1s2, z3);
    z3 = fmaf(A3[12], C1, z3);

    // head in log2 domain + softmax via ex2.approx / rcp.approx
    float eo[6];
    #pragma unroll
    for (int k = 0; k < 6; k++) {
        float4 w = W4[k];
        float acc = bs[k];
        acc = fmaf(w.x, z0, acc);
        acc = fmaf(w.y, z1, acc);
        acc = fmaf(w.z, z2, acc);
        acc = fmaf(w.w, z3, acc);
        eo[k] = ex2_approx(acc);
    }
    float ssum = ((eo[0] + eo[1]) + (eo[2] + eo[3])) + (eo[4] + eo[5]);
    float inv = rcp_approx(ssum);

    bool fullblk = (blockIdx.x * 256 + 256) <= B;   // uniform per block
    if (fullblk) {
        // stage 6 floats/thread in smem, then fully coalesced STG.128
        float2* s2 = (float2*)obuf;
        s2[t * 3 + 0] = make_float2(eo[0] * inv, eo[1] * inv);
        s2[t * 3 + 1] = make_float2(eo[2] * inv, eo[3] * inv);
        s2[t * 3 + 2] = make_float2(eo[4] * inv, eo[5] * inv);
        __syncthreads();
        float4* o4 = (float4*)out + (size_t)blockIdx.x * 384;
        const float4* s4 = (const float4*)obuf;
        o4[t] = s4[t];
        int j = t + 256;
        if (j < 384) o4[j] = s4[j];
    } else if (i < B) {
        float2* o2 = (float2*)out;
        o2[i * 3 + 0] = make_float2(eo[0] * inv, eo[1] * inv);
        o2[i * 3 + 1] = make_float2(eo[2] * inv, eo[3] * inv);
        o2[i * 3 + 2] = make_float2(eo[4] * inv, eo[5] * inv);
    }
}

extern "C" void kernel_launch(void* const* d_in, const int* in_sizes, int n_in,
                              void* d_out, int out_size) {
    const float4* x  = (const float4*)d_in[0];
    const float*  qw = (const float*)d_in[1];
    const float*  W  = (const float*)d_in[2];
    const float*  b  = (const float*)d_in[3];
    float* out = (float*)d_out;
    int B = in_sizes[0] / 4;
    int threads = 256;
    int blocks = (B + threads - 1) / threads;
    qnn_kernel<<<blocks, threads>>>(x, qw, W, b, out, B);
}